// round 1
// baseline (speedup 1.0000x reference)
#include <cuda_runtime.h>

#define B_   8
#define C_   192
#define CQ   32
#define N_   16384
#define NPIX (B_ * N_)
#define EPSF 1e-6f

typedef unsigned long long u64;

// ---------------- scratch (device globals; no allocation allowed) ----------
__device__ float g_Qn[(size_t)NPIX * CQ];     // [b][n][32] normalized Q, pixel-major
__device__ float g_Kn[(size_t)NPIX * CQ];     // [b][n][32] normalized K, pixel-major
__device__ float g_G[B_ * CQ * C_];           // G[b][m][k] = sum_n Kn[b,m,n] * x[b,k,n]
__device__ float g_KS[B_ * CQ];               // Kn.sum over n
__device__ float g_xsum[B_ * C_];             // sum_n x[b,c,n]
__device__ float g_M[B_ * CQ * C_];           // matrix[b][m][c]
__device__ float g_VS[B_ * C_];               // value_sum[b][c]

// ---------------- f32x2 helpers --------------------------------------------
__device__ __forceinline__ u64 pack2(float lo, float hi) {
    u64 r;
    asm("mov.b64 %0, {%1, %2};" : "=l"(r)
        : "r"(__float_as_uint(lo)), "r"(__float_as_uint(hi)));
    return r;
}
__device__ __forceinline__ void unpack2(u64 v, float& lo, float& hi) {
    unsigned a, b;
    asm("mov.b64 {%0, %1}, %2;" : "=r"(a), "=r"(b) : "l"(v));
    lo = __uint_as_float(a); hi = __uint_as_float(b);
}
__device__ __forceinline__ void fma2(u64& d, u64 a, u64 b) {
    asm("fma.rn.f32x2 %0, %1, %2, %0;" : "+l"(d) : "l"(a), "l"(b));
}
__device__ __forceinline__ u64 mul2(u64 a, u64 b) {
    u64 r; asm("mul.rn.f32x2 %0, %1, %2;" : "=l"(r) : "l"(a), "l"(b));
    return r;
}

// ---------------- K0: zero accumulators ------------------------------------
__global__ void k_zero() {
    int i = blockIdx.x * 256 + threadIdx.x;
    if (i < B_ * CQ * C_) g_G[i] = 0.0f;
    if (i < B_ * CQ)      g_KS[i] = 0.0f;
    if (i < B_ * C_)      g_xsum[i] = 0.0f;
}

// ---------------- K1: Q/K projection + L2 normalize + KSum -----------------
// one thread per pixel; weights packed as float2 over output-channel pairs in
// SMEM; inner loop is 1 LDG + 32 broadcast LDS.64 + 32 FMA2 per input channel.
__global__ void __launch_bounds__(256) k_qk(
    const float* __restrict__ x1,
    const float* __restrict__ Wq, const float* __restrict__ bq,
    const float* __restrict__ Wk, const float* __restrict__ bk)
{
    __shared__ __align__(16) float2 sWq[C_][CQ / 2];   // 24 KB
    __shared__ __align__(16) float2 sWk[C_][CQ / 2];   // 24 KB
    int tid = threadIdx.x;

    for (int i = tid; i < C_ * (CQ / 2); i += 256) {
        int c = i / (CQ / 2), k = i % (CQ / 2);
        sWq[c][k] = make_float2(Wq[(2 * k) * C_ + c], Wq[(2 * k + 1) * C_ + c]);
        sWk[c][k] = make_float2(Wk[(2 * k) * C_ + c], Wk[(2 * k + 1) * C_ + c]);
    }
    __syncthreads();

    int pixel = blockIdx.x * 256 + tid;
    int b = pixel >> 14;            // / N_
    int n = pixel & (N_ - 1);
    const float* xp = x1 + (size_t)b * C_ * N_ + n;

    u64 accq[16], acck[16];
#pragma unroll
    for (int k = 0; k < 16; k++) {
        accq[k] = pack2(bq[2 * k], bq[2 * k + 1]);
        acck[k] = pack2(bk[2 * k], bk[2 * k + 1]);
    }

#pragma unroll 4
    for (int c = 0; c < C_; c++) {
        float xv = xp[(size_t)c * N_];
        u64 xv2 = pack2(xv, xv);
#pragma unroll
        for (int k = 0; k < 16; k++) {
            fma2(accq[k], *reinterpret_cast<const u64*>(&sWq[c][k]), xv2);
            fma2(acck[k], *reinterpret_cast<const u64*>(&sWk[c][k]), xv2);
        }
    }

    float q[CQ], kk[CQ];
#pragma unroll
    for (int k = 0; k < 16; k++) {
        unpack2(accq[k], q[2 * k], q[2 * k + 1]);
        unpack2(acck[k], kk[2 * k], kk[2 * k + 1]);
    }
    float sq = 0.f, sk = 0.f;
#pragma unroll
    for (int m = 0; m < CQ; m++) { sq += q[m] * q[m]; sk += kk[m] * kk[m]; }
    float rq = rsqrtf(sq), rk = rsqrtf(sk);
#pragma unroll
    for (int m = 0; m < CQ; m++) { q[m] *= rq; kk[m] *= rk; }

    float4* qo = reinterpret_cast<float4*>(g_Qn + (size_t)pixel * CQ);
    float4* ko = reinterpret_cast<float4*>(g_Kn + (size_t)pixel * CQ);
#pragma unroll
    for (int j = 0; j < 8; j++) {
        qo[j] = make_float4(q[4 * j], q[4 * j + 1], q[4 * j + 2], q[4 * j + 3]);
        ko[j] = make_float4(kk[4 * j], kk[4 * j + 1], kk[4 * j + 2], kk[4 * j + 3]);
    }

    // KSum: warp reduce per channel, one REDG per warp per channel
#pragma unroll
    for (int m = 0; m < CQ; m++) {
        float v = kk[m];
        v += __shfl_xor_sync(0xffffffffu, v, 16);
        v += __shfl_xor_sync(0xffffffffu, v, 8);
        v += __shfl_xor_sync(0xffffffffu, v, 4);
        v += __shfl_xor_sync(0xffffffffu, v, 2);
        v += __shfl_xor_sync(0xffffffffu, v, 1);
        if ((tid & 31) == 0) atomicAdd(&g_KS[b * CQ + m], v);
    }
}

// ---------------- K2: G = Kn @ x^T (per batch) + xsum ----------------------
// 512 blocks: 64 slices/batch * 256 pixels, processed in 8 tiles of 32 pixels.
// lane = m (0..31), warp = c2 group (12 channel-pairs each).
__global__ void __launch_bounds__(256) k_gmat(const float* __restrict__ x)
{
    __shared__ __align__(16) float sXT[32][194];  // [p][c], padded (2-way max)
    __shared__ __align__(16) float sKn[32][32];   // [p][m]
    int tid = threadIdx.x;
    int w = tid >> 5, p = tid & 31;
    int b = blockIdx.x >> 6;
    int slice = blockIdx.x & 63;
    int n_base = slice * 256;

    u64 acc[12];
#pragma unroll
    for (int j = 0; j < 12; j++) acc[j] = 0ULL;
    float xs[24];
#pragma unroll
    for (int j = 0; j < 24; j++) xs[j] = 0.f;

    const float* xb = x + (size_t)b * C_ * N_;
    const float* knb = g_Kn + (size_t)b * N_ * CQ;

    for (int t = 0; t < 8; t++) {
        int n0 = n_base + t * 32;
        __syncthreads();
        // x tile, transposed into SMEM; also xsum partials
#pragma unroll
        for (int j = 0; j < 24; j++) {
            int c = w + 8 * j;
            float v = xb[(size_t)c * N_ + n0 + p];
            sXT[p][c] = v;
            xs[j] += v;
        }
        // Kn tile (32 pixels x 32 ch), coalesced float4 copy
        reinterpret_cast<float4*>(&sKn[0][0])[tid] =
            reinterpret_cast<const float4*>(knb + (size_t)n0 * CQ)[tid];
        __syncthreads();

#pragma unroll 4
        for (int pp = 0; pp < 32; pp++) {
            float kv = sKn[pp][p];          // lane==m, conflict-free
            u64 kv2 = pack2(kv, kv);
#pragma unroll
            for (int j = 0; j < 12; j++) {
                int c2 = w * 12 + j;
                u64 xv2 = *reinterpret_cast<const u64*>(&sXT[pp][2 * c2]); // broadcast
                fma2(acc[j], kv2, xv2);
            }
        }
    }

#pragma unroll
    for (int j = 0; j < 12; j++) {
        float lo, hi; unpack2(acc[j], lo, hi);
        int c = (w * 12 + j) * 2;
        atomicAdd(&g_G[b * CQ * C_ + p * C_ + c],     lo);
        atomicAdd(&g_G[b * CQ * C_ + p * C_ + c + 1], hi);
    }
#pragma unroll
    for (int j = 0; j < 24; j++) {
        float v = xs[j];
        v += __shfl_xor_sync(0xffffffffu, v, 16);
        v += __shfl_xor_sync(0xffffffffu, v, 8);
        v += __shfl_xor_sync(0xffffffffu, v, 4);
        v += __shfl_xor_sync(0xffffffffu, v, 2);
        v += __shfl_xor_sync(0xffffffffu, v, 1);
        if (p == 0) atomicAdd(&g_xsum[b * C_ + w + 8 * j], v);
    }
}

// ---------------- K2b: matrix = G @ Wv^T + KS (x) bv; value_sum ------------
// 48 blocks: (b, ctile of 32 columns)
__global__ void __launch_bounds__(256) k_small(
    const float* __restrict__ Wv, const float* __restrict__ bv)
{
    __shared__ __align__(16) float sG[CQ][196];   // padded for LDS.128 phases
    __shared__ __align__(16) float sWt[32][C_];
    int tid = threadIdx.x;
    int b = blockIdx.x / 6;
    int ct = blockIdx.x % 6;

    for (int i = tid; i < CQ * C_; i += 256)
        sG[i / C_][i % C_] = g_G[b * CQ * C_ + i];
    for (int i = tid; i < 32 * C_; i += 256)
        sWt[i / C_][i % C_] = Wv[ct * 32 * C_ + i];
    __syncthreads();

    for (int o = tid; o < CQ * 32; o += 256) {
        int m = o & 31;
        int cl = o >> 5;
        const float4* gr = reinterpret_cast<const float4*>(&sG[m][0]);
        const float4* wr = reinterpret_cast<const float4*>(&sWt[cl][0]);
        float acc = 0.f;
#pragma unroll 8
        for (int k = 0; k < C_ / 4; k++) {
            float4 a = gr[k], v = wr[k];
            acc += a.x * v.x + a.y * v.y + a.z * v.z + a.w * v.w;
        }
        int c = ct * 32 + cl;
        g_M[b * CQ * C_ + m * C_ + c] = acc + g_KS[b * CQ + m] * bv[c];
    }

    if (tid < 32) {
        int c = ct * 32 + tid;
        const float* xsp = g_xsum + b * C_;
        float acc = 0.f;
#pragma unroll 8
        for (int k = 0; k < C_; k++) acc += sWt[tid][k] * xsp[k];
        g_VS[b * C_ + c] = acc + (float)N_ * bv[c];
    }
}

// ---------------- K3: tailor_sum + output ----------------------------------
__global__ void __launch_bounds__(256) k_out(
    const float* __restrict__ gamma, float* __restrict__ out)
{
    __shared__ __align__(16) float sM[CQ][C_];   // 24 KB
    __shared__ __align__(16) float sVS[C_];
    __shared__ float sKS[CQ];
    int tid = threadIdx.x;
    int pixel = blockIdx.x * 256 + tid;
    int b = pixel >> 14;
    int n = pixel & (N_ - 1);

    for (int i = tid; i < CQ * C_ / 4; i += 256)
        reinterpret_cast<float4*>(&sM[0][0])[i] =
            reinterpret_cast<const float4*>(g_M + b * CQ * C_)[i];
    if (tid < C_) sVS[tid] = g_VS[b * C_ + tid];
    if (tid < CQ) sKS[tid] = g_KS[b * CQ + tid] + EPSF;
    __syncthreads();

    float qn[CQ];
    const float4* qp = reinterpret_cast<const float4*>(g_Qn + (size_t)pixel * CQ);
#pragma unroll
    for (int j = 0; j < 8; j++) {
        float4 v = qp[j];
        qn[4 * j] = v.x; qn[4 * j + 1] = v.y; qn[4 * j + 2] = v.z; qn[4 * j + 3] = v.w;
    }

    float dot = 0.f;
#pragma unroll
    for (int m = 0; m < CQ; m++) dot += qn[m] * sKS[m];
    float ts = 1.0f / ((float)N_ + dot);
    float g = gamma[0] * ts;

    u64 a2[CQ];
#pragma unroll
    for (int m = 0; m < CQ; m++) {
        float am = qn[m] * g;
        a2[m] = pack2(am, am);
    }
    u64 g2 = pack2(g, g);

    float* ob = out + (size_t)b * C_ * N_ + n;
#pragma unroll 2
    for (int c2 = 0; c2 < C_ / 2; c2++) {
        u64 acc = mul2(g2, *reinterpret_cast<const u64*>(&sVS[2 * c2]));
#pragma unroll
        for (int m = 0; m < CQ; m++)
            fma2(acc, a2[m], *reinterpret_cast<const u64*>(&sM[m][2 * c2])); // broadcast
        float lo, hi; unpack2(acc, lo, hi);
        ob[(size_t)(2 * c2) * N_]     = lo;
        ob[(size_t)(2 * c2 + 1) * N_] = hi;
    }
}

// ---------------- launch -----------------------------------------------------
extern "C" void kernel_launch(void* const* d_in, const int* in_sizes, int n_in,
                              void* d_out, int out_size)
{
    const float* x     = (const float*)d_in[0];
    const float* x1    = (const float*)d_in[1];
    const float* Wq    = (const float*)d_in[2];
    const float* bq    = (const float*)d_in[3];
    const float* Wk    = (const float*)d_in[4];
    const float* bk    = (const float*)d_in[5];
    const float* Wv    = (const float*)d_in[6];
    const float* bv    = (const float*)d_in[7];
    const float* gamma = (const float*)d_in[8];
    float* out = (float*)d_out;

    k_zero<<<(B_ * CQ * C_ + 255) / 256, 256>>>();
    k_qk<<<NPIX / 256, 256>>>(x1, Wq, bq, Wk, bk);
    k_gmat<<<512, 256>>>(x);
    k_small<<<48, 256>>>(Wv, bv);
    k_out<<<NPIX / 256, 256>>>(gamma, out);
}

// round 2
// speedup vs baseline: 1.3295x; 1.3295x over previous
#include <cuda_runtime.h>

#define B_   8
#define C_   192
#define CQ   32
#define N_   16384
#define NPIX (B_ * N_)
#define EPSF 1e-6f

typedef unsigned long long u64;

// ---------------- scratch ---------------------------------------------------
__device__ float g_Qn[(size_t)NPIX * CQ];   // [px][32] normalized Q
__device__ float g_Kn[(size_t)NPIX * CQ];   // [px][32] normalized K
__device__ float g_G[B_ * 33 * C_];         // rows 0..31: G[m][k]=sum_n Kn*x ; row 32: xsum[k]
__device__ float g_KS[B_ * CQ];             // sum_n Kn
__device__ float g_M[B_ * 33 * C_];         // rows 0..31: matrix[m][c]; row 32: value_sum[c]

// ---------------- f32x2 helpers ---------------------------------------------
__device__ __forceinline__ u64 pack2(float lo, float hi) {
    u64 r;
    asm("mov.b64 %0, {%1, %2};" : "=l"(r)
        : "r"(__float_as_uint(lo)), "r"(__float_as_uint(hi)));
    return r;
}
__device__ __forceinline__ void unpack2(u64 v, float& lo, float& hi) {
    unsigned a, b;
    asm("mov.b64 {%0, %1}, %2;" : "=r"(a), "=r"(b) : "l"(v));
    lo = __uint_as_float(a); hi = __uint_as_float(b);
}
__device__ __forceinline__ void fma2(u64& d, u64 a, u64 b) {
    asm("fma.rn.f32x2 %0, %1, %2, %0;" : "+l"(d) : "l"(a), "l"(b));
}
__device__ __forceinline__ void red2(float* p, float lo, float hi) {
    asm volatile("red.global.add.v2.f32 [%0], {%1, %2};"
                 :: "l"(p), "f"(lo), "f"(hi) : "memory");
}

// ---------------- K0: zero accumulators --------------------------------------
__global__ void k_zero() {
    int i = blockIdx.x * 256 + threadIdx.x;
    if (i < B_ * 33 * C_) g_G[i] = 0.0f;
    if (i < B_ * CQ)      g_KS[i] = 0.0f;
}

// ---------------- K1: Q/K projection + L2 norm + KSum ------------------------
// Register-tiled GEMM: M=131072 px, N=64 out (32 pairs), K=192.
// Block: 256 px tile. Thread: 4 px (stride 64) x 8 out-pairs. col=tid&3 picks
// the out-pair group (col 0,1 -> Q halves; col 2,3 -> K halves).
__global__ void __launch_bounds__(256) k_qk(
    const float* __restrict__ x1,
    const float* __restrict__ Wq, const float* __restrict__ bq,
    const float* __restrict__ Wk, const float* __restrict__ bk)
{
    extern __shared__ float sm[];
    float2* sW = (float2*)sm;              // [192][32] out-pairs     (48 KB)
    float*  sX = sm + 2 * C_ * CQ;         // [16][256]               (16 KB)
    __shared__ float sKSb[CQ];

    int tid = threadIdx.x;
    int col = tid & 3, row = tid >> 2;
    int b   = blockIdx.x >> 6;
    int n0  = (blockIdx.x << 8) & (N_ - 1);
    const float* xb = x1 + (size_t)b * C_ * N_ + n0;

    // stage weights: sW[c][o] = (W[2o][c], W[2o+1][c]); o<16 -> Wq, else Wk
    for (int i = tid; i < C_ * CQ; i += 256) {
        int c = i >> 5, o = i & 31;
        float lo, hi;
        if (o < 16) { lo = Wq[(2 * o) * C_ + c];        hi = Wq[(2 * o + 1) * C_ + c]; }
        else { int oo = o - 16; lo = Wk[(2 * oo) * C_ + c]; hi = Wk[(2 * oo + 1) * C_ + c]; }
        sW[c * CQ + o] = make_float2(lo, hi);
    }
    if (tid < CQ) sKSb[tid] = 0.f;

    u64 acc[4][8];
    {
        int ob = col * 8;
#pragma unroll
        for (int j = 0; j < 8; j++) {
            int o = ob + j;
            float lo, hi;
            if (o < 16) { lo = bq[2 * o]; hi = bq[2 * o + 1]; }
            else        { lo = bk[2 * (o - 16)]; hi = bk[2 * (o - 16) + 1]; }
            u64 v = pack2(lo, hi);
#pragma unroll
            for (int i = 0; i < 4; i++) acc[i][j] = v;
        }
    }

    for (int ks = 0; ks < C_; ks += 16) {
        __syncthreads();
#pragma unroll
        for (int t = 0; t < 16; t++)
            sX[t * 256 + tid] = xb[(size_t)(ks + t) * N_ + tid];
        __syncthreads();
#pragma unroll
        for (int t = 0; t < 16; t++) {
            u64 w2[8];
#pragma unroll
            for (int j = 0; j < 8; j++)
                w2[j] = *(const u64*)&sW[(ks + t) * CQ + col * 8 + j];
#pragma unroll
            for (int i = 0; i < 4; i++) {
                float xv = sX[t * 256 + row + 64 * i];
                u64 xv2 = pack2(xv, xv);
#pragma unroll
                for (int j = 0; j < 8; j++) fma2(acc[i][j], w2[j], xv2);
            }
        }
    }

    // epilogue: unpack, L2-normalize per pixel (halves joined via shfl_xor 1)
    float v[4][16], s[4];
#pragma unroll
    for (int i = 0; i < 4; i++) {
        s[i] = 0.f;
#pragma unroll
        for (int j = 0; j < 8; j++) {
            unpack2(acc[i][j], v[i][2 * j], v[i][2 * j + 1]);
            s[i] += v[i][2 * j] * v[i][2 * j] + v[i][2 * j + 1] * v[i][2 * j + 1];
        }
    }
#pragma unroll
    for (int i = 0; i < 4; i++) {
        s[i] += __shfl_xor_sync(0xffffffffu, s[i], 1);
        float r = rsqrtf(s[i]);
#pragma unroll
        for (int t = 0; t < 16; t++) v[i][t] *= r;
    }

    float* dst = (col < 2) ? g_Qn : g_Kn;
    int half = (col & 1) << 4;
    int pxb = blockIdx.x * 256 + row;
#pragma unroll
    for (int i = 0; i < 4; i++) {
        float4* o4 = (float4*)(dst + (size_t)(pxb + 64 * i) * CQ + half);
#pragma unroll
        for (int jj = 0; jj < 4; jj++)
            o4[jj] = make_float4(v[i][4 * jj], v[i][4 * jj + 1],
                                 v[i][4 * jj + 2], v[i][4 * jj + 3]);
    }

    // KSum (K halves only): sum 4 px locally, reduce 8 rows in warp, smem, global
    float ks2[16];
#pragma unroll
    for (int t = 0; t < 16; t++)
        ks2[t] = v[0][t] + v[1][t] + v[2][t] + v[3][t];
#pragma unroll
    for (int t = 0; t < 16; t++) {
        ks2[t] += __shfl_xor_sync(0xffffffffu, ks2[t], 4);
        ks2[t] += __shfl_xor_sync(0xffffffffu, ks2[t], 8);
        ks2[t] += __shfl_xor_sync(0xffffffffu, ks2[t], 16);
    }
    if (col >= 2 && ((tid >> 2) & 7) == 0) {
        int mb = (col - 2) << 4;
#pragma unroll
        for (int t = 0; t < 16; t++) atomicAdd(&sKSb[mb + t], ks2[t]);
    }
    __syncthreads();
    if (tid < CQ) atomicAdd(&g_KS[b * CQ + tid], sKSb[tid]);
}

// ---------------- K2: G = Kn @ x^T  (+ xsum) ---------------------------------
// 512 blocks = 8 b x 64 n-slices of 256. 128 threads: mg=tid>>4 (4 m's),
// cg=tid&15 (6 c-pairs). Thread tile 4m x 6c2 -> 24 FMA2 per 7 LDS.
__global__ void __launch_bounds__(128) k_gmat(const float* __restrict__ x)
{
    __shared__ __align__(16) float sXT[32][194];
    __shared__ __align__(16) float sKn[32][32];
    int tid = threadIdx.x;
    int w = tid >> 5, p = tid & 31;
    int mg = tid >> 4, cg = tid & 15;
    int b  = blockIdx.x >> 6;
    int n0 = (blockIdx.x & 63) << 8;

    const float* xb = x + (size_t)b * C_ * N_ + n0;
    const float4* knb = (const float4*)(g_Kn + ((size_t)b * N_ + n0) * CQ);

    u64 acc[4][6];
#pragma unroll
    for (int mi = 0; mi < 4; mi++)
#pragma unroll
        for (int j = 0; j < 6; j++) acc[mi][j] = 0ULL;
    float xs[48];
#pragma unroll
    for (int j = 0; j < 48; j++) xs[j] = 0.f;

    for (int s = 0; s < 8; s++) {
        __syncthreads();
#pragma unroll
        for (int j = 0; j < 48; j++) {
            int c = w * 48 + j;
            float vx = xb[(size_t)c * N_ + s * 32 + p];
            sXT[p][c] = vx;
            xs[j] += vx;
        }
        {
            const float4* src = knb + s * 256;
            float4* d = (float4*)&sKn[0][0];
            d[tid] = src[tid];
            d[tid + 128] = src[tid + 128];
        }
        __syncthreads();
#pragma unroll 4
        for (int pp = 0; pp < 32; pp++) {
            float4 kv = *(const float4*)&sKn[pp][mg * 4];
            u64 k2a = pack2(kv.x, kv.x), k2b = pack2(kv.y, kv.y);
            u64 k2c = pack2(kv.z, kv.z), k2d = pack2(kv.w, kv.w);
#pragma unroll
            for (int j = 0; j < 6; j++) {
                u64 xv2 = *(const u64*)&sXT[pp][2 * (cg * 6 + j)];
                fma2(acc[0][j], k2a, xv2);
                fma2(acc[1][j], k2b, xv2);
                fma2(acc[2][j], k2c, xv2);
                fma2(acc[3][j], k2d, xv2);
            }
        }
    }

    float* gb = g_G + b * 33 * C_;
#pragma unroll
    for (int mi = 0; mi < 4; mi++)
#pragma unroll
        for (int j = 0; j < 6; j++) {
            float lo, hi; unpack2(acc[mi][j], lo, hi);
            red2(gb + (mg * 4 + mi) * C_ + 2 * (cg * 6 + j), lo, hi);
        }
#pragma unroll
    for (int j = 0; j < 48; j++) {
        float vv = xs[j];
        vv += __shfl_xor_sync(0xffffffffu, vv, 16);
        vv += __shfl_xor_sync(0xffffffffu, vv, 8);
        vv += __shfl_xor_sync(0xffffffffu, vv, 4);
        vv += __shfl_xor_sync(0xffffffffu, vv, 2);
        vv += __shfl_xor_sync(0xffffffffu, vv, 1);
        if (p == 0) atomicAdd(gb + 32 * C_ + w * 48 + j, vv);
    }
}

// ---------------- K3: M' = Ghat @ Wv^T + outer(coef, bv) ---------------------
// 264 blocks = 8 b x 33 rows; 192 threads = one output column each.
__global__ void __launch_bounds__(192) k_small(
    const float* __restrict__ Wv, const float* __restrict__ bv)
{
    __shared__ __align__(16) float sG[C_];
    int tid = threadIdx.x;
    int b = blockIdx.x / 33;
    int r = blockIdx.x % 33;
    if (tid < 48)
        ((float4*)sG)[tid] = ((const float4*)(g_G + (b * 33 + r) * C_))[tid];
    __syncthreads();

    const float4* wr = (const float4*)(Wv + (size_t)tid * C_);
    const float4* g4 = (const float4*)sG;
    float a0 = 0.f, a1 = 0.f, a2 = 0.f, a3 = 0.f;
#pragma unroll 8
    for (int k = 0; k < 48; k++) {
        float4 wv = wr[k];
        float4 gg = g4[k];
        a0 += wv.x * gg.x; a1 += wv.y * gg.y;
        a2 += wv.z * gg.z; a3 += wv.w * gg.w;
    }
    float coef = (r < 32) ? g_KS[b * CQ + r] : (float)N_;
    g_M[(b * 33 + r) * C_ + tid] = (a0 + a1) + (a2 + a3) + coef * bv[tid];
}

// ---------------- K4: output GEMM out[n,c] = A[n,0..32] @ M'[0..32,c] ---------
// A[n][m]=g(n)*Qn[n][m], A[n][32]=g(n), M' row 32 = VS. g computed in prologue.
// 1024 blocks x 256 thr; 128-px tile. rw=tid&31 (4 px, stride 32), cg=tid>>5
// (12 c-pairs). Stores fully coalesced along n.
__global__ void __launch_bounds__(256) k_out(
    const float* __restrict__ gamma, float* __restrict__ out)
{
    extern __shared__ float sm[];
    float* sM = sm;                        // [33][192]         6336 f
    u64*  sA  = (u64*)(sm + 6336);         // [128][33] (a,a)   8448 f
    float* sQ = sm + 6336 + 8448;          // [128][33] padded  4224 f
    __shared__ float sKS[CQ];
    int tid = threadIdx.x;
    int b  = blockIdx.x >> 7;
    int n0 = (blockIdx.x << 7) & (N_ - 1);

    const float4* msrc = (const float4*)(g_M + b * 33 * C_);
    float4* md = (float4*)sM;
    for (int i = tid; i < 1584; i += 256) md[i] = msrc[i];
    const float4* qsrc = (const float4*)(g_Qn + ((size_t)b * N_ + n0) * CQ);
    for (int i = tid; i < 1024; i += 256) {
        float4 qv = qsrc[i];
        int px = i >> 3, qo = (i & 7) * 4;
        float* d = sQ + px * 33 + qo;
        d[0] = qv.x; d[1] = qv.y; d[2] = qv.z; d[3] = qv.w;
    }
    if (tid < CQ) sKS[tid] = g_KS[b * CQ + tid] + EPSF;
    __syncthreads();

    if (tid < 128) {
        float dot = 0.f, qv[CQ];
#pragma unroll
        for (int m = 0; m < CQ; m++) { qv[m] = sQ[tid * 33 + m]; dot += qv[m] * sKS[m]; }
        float g = gamma[0] / ((float)N_ + dot);
#pragma unroll
        for (int m = 0; m < CQ; m++) sA[tid * 33 + m] = pack2(qv[m] * g, qv[m] * g);
        sA[tid * 33 + 32] = pack2(g, g);
    }
    __syncthreads();

    int rw = tid & 31, cg = tid >> 5;
    u64 acc[4][12];
#pragma unroll
    for (int i = 0; i < 4; i++)
#pragma unroll
        for (int j = 0; j < 12; j++) acc[i][j] = 0ULL;

#pragma unroll 3
    for (int k = 0; k < 33; k++) {
        u64 a2[4];
#pragma unroll
        for (int i = 0; i < 4; i++) a2[i] = sA[(rw + 32 * i) * 33 + k];
        const u64* mrow = (const u64*)(sM + k * C_) + cg * 12;
#pragma unroll
        for (int j = 0; j < 12; j++) {
            u64 m2 = mrow[j];
#pragma unroll
            for (int i = 0; i < 4; i++) fma2(acc[i][j], a2[i], m2);
        }
    }

    float* ob = out + (size_t)b * C_ * N_ + n0 + rw;
#pragma unroll
    for (int i = 0; i < 4; i++)
#pragma unroll
        for (int j = 0; j < 12; j++) {
            float lo, hi; unpack2(acc[i][j], lo, hi);
            int c = 2 * (cg * 12 + j);
            ob[(size_t)c * N_ + 32 * i] = lo;
            ob[(size_t)(c + 1) * N_ + 32 * i] = hi;
        }
}

// ---------------- launch ------------------------------------------------------
extern "C" void kernel_launch(void* const* d_in, const int* in_sizes, int n_in,
                              void* d_out, int out_size)
{
    const float* x     = (const float*)d_in[0];
    const float* x1    = (const float*)d_in[1];
    const float* Wq    = (const float*)d_in[2];
    const float* bq    = (const float*)d_in[3];
    const float* Wk    = (const float*)d_in[4];
    const float* bk    = (const float*)d_in[5];
    const float* Wv    = (const float*)d_in[6];
    const float* bv    = (const float*)d_in[7];
    const float* gamma = (const float*)d_in[8];
    float* out = (float*)d_out;

    cudaFuncSetAttribute(k_qk,  cudaFuncAttributeMaxDynamicSharedMemorySize, 65536);
    cudaFuncSetAttribute(k_out, cudaFuncAttributeMaxDynamicSharedMemorySize, 76032);

    k_zero<<<198, 256>>>();
    k_qk  <<<512, 256, 65536>>>(x1, Wq, bq, Wk, bk);
    k_gmat<<<512, 128>>>(x);
    k_small<<<264, 192>>>(Wv, bv);
    k_out <<<1024, 256, 76032>>>(gamma, out);
}

// round 3
// speedup vs baseline: 1.5019x; 1.1296x over previous
#include <cuda_runtime.h>

#define B_   8
#define C_   192
#define CQ   32
#define N_   16384
#define NPIX (B_ * N_)
#define EPSF 1e-6f

typedef unsigned long long u64;

// ---------------- scratch ---------------------------------------------------
__device__ float g_Qn[(size_t)NPIX * CQ];   // [px][32] normalized Q
__device__ float g_Kn[(size_t)NPIX * CQ];   // [px][32] normalized K
__device__ float g_G[B_ * 33 * C_];         // rows 0..31: G[m][k]; row 32: xsum[k]
__device__ float g_KS[B_ * CQ];             // sum_n Kn
__device__ float g_M[B_ * 33 * C_];         // rows 0..31: matrix[m][c]; row 32: value_sum[c]

// ---------------- f32x2 helpers ---------------------------------------------
__device__ __forceinline__ u64 pack2(float lo, float hi) {
    u64 r;
    asm("mov.b64 %0, {%1, %2};" : "=l"(r)
        : "r"(__float_as_uint(lo)), "r"(__float_as_uint(hi)));
    return r;
}
__device__ __forceinline__ void unpack2(u64 v, float& lo, float& hi) {
    unsigned a, b;
    asm("mov.b64 {%0, %1}, %2;" : "=r"(a), "=r"(b) : "l"(v));
    lo = __uint_as_float(a); hi = __uint_as_float(b);
}
__device__ __forceinline__ void fma2(u64& d, u64 a, u64 b) {
    asm("fma.rn.f32x2 %0, %1, %2, %0;" : "+l"(d) : "l"(a), "l"(b));
}
__device__ __forceinline__ void red2(float* p, float lo, float hi) {
    asm volatile("red.global.add.v2.f32 [%0], {%1, %2};"
                 :: "l"(p), "f"(lo), "f"(hi) : "memory");
}

// ---------------- K1: Q/K projection + L2 norm (also zeroes G/KS) ------------
// Register-tiled: 256-px block tile; thread = 4 px x 8 out-pairs.
// Weights in smem padded in groups of 9 pairs -> conflict-free broadcast LDS.64.
__global__ void __launch_bounds__(256) k_qk(
    const float* __restrict__ x1,
    const float* __restrict__ Wq, const float* __restrict__ bq,
    const float* __restrict__ Wk, const float* __restrict__ bk)
{
    extern __shared__ float sm[];
    float2* sW = (float2*)sm;              // [192][36] pair-groups of 9  (55296 B)
    float*  sX = sm + 2 * C_ * 36;         // [16][256]                   (16384 B)

    int tid = threadIdx.x;
    int col = tid & 3, row = tid >> 2;
    int b   = blockIdx.x >> 6;
    int n0  = (blockIdx.x & 63) << 8;
    const float* xb = x1 + (size_t)b * C_ * N_ + n0;

    // zero accumulators for k_gmat (disjoint ranges; k_qk never reads them)
    {
        int z = blockIdx.x * 256 + tid;
        if (z < B_ * 33 * C_) g_G[z] = 0.0f;
        int zk = z - B_ * 33 * C_;
        if (zk >= 0 && zk < B_ * CQ) g_KS[zk] = 0.0f;
    }

    // stage weights: group g (0..3), pair j (0..7) at sW[c*36 + g*9 + j]
    for (int i = tid; i < C_ * CQ; i += 256) {
        int o = i / C_, c = i % C_;        // coalesced in c
        int g = o >> 3, j = o & 7;
        float lo, hi;
        if (o < 16) { lo = Wq[(2 * o) * C_ + c];           hi = Wq[(2 * o + 1) * C_ + c]; }
        else { int oo = o - 16; lo = Wk[(2 * oo) * C_ + c]; hi = Wk[(2 * oo + 1) * C_ + c]; }
        sW[c * 36 + g * 9 + j] = make_float2(lo, hi);
    }

    u64 acc[4][8];
    {
#pragma unroll
        for (int j = 0; j < 8; j++) {
            int o = col * 8 + j;
            float lo, hi;
            if (o < 16) { lo = bq[2 * o]; hi = bq[2 * o + 1]; }
            else        { lo = bk[2 * (o - 16)]; hi = bk[2 * (o - 16) + 1]; }
            u64 v = pack2(lo, hi);
#pragma unroll
            for (int i = 0; i < 4; i++) acc[i][j] = v;
        }
    }

    for (int ks = 0; ks < C_; ks += 16) {
        __syncthreads();
#pragma unroll
        for (int t = 0; t < 16; t++)
            sX[t * 256 + tid] = xb[(size_t)(ks + t) * N_ + tid];
        __syncthreads();
#pragma unroll
        for (int t = 0; t < 16; t++) {
            u64 w2[8];
#pragma unroll
            for (int j = 0; j < 8; j++)
                w2[j] = *(const u64*)&sW[(ks + t) * 36 + col * 9 + j];
#pragma unroll
            for (int i = 0; i < 4; i++) {
                float xv = sX[t * 256 + row + 64 * i];
                u64 xv2 = pack2(xv, xv);
#pragma unroll
                for (int j = 0; j < 8; j++) fma2(acc[i][j], w2[j], xv2);
            }
        }
    }

    // epilogue: unpack, L2 normalize (halves joined via shfl_xor 1)
    float v[4][16], s[4];
#pragma unroll
    for (int i = 0; i < 4; i++) {
        s[i] = 0.f;
#pragma unroll
        for (int j = 0; j < 8; j++) {
            unpack2(acc[i][j], v[i][2 * j], v[i][2 * j + 1]);
            s[i] += v[i][2 * j] * v[i][2 * j] + v[i][2 * j + 1] * v[i][2 * j + 1];
        }
    }
#pragma unroll
    for (int i = 0; i < 4; i++) {
        s[i] += __shfl_xor_sync(0xffffffffu, s[i], 1);
        float r = rsqrtf(s[i]);
#pragma unroll
        for (int t = 0; t < 16; t++) v[i][t] *= r;
    }

    float* dst = (col < 2) ? g_Qn : g_Kn;
    int half = (col & 1) << 4;
    int pxb = blockIdx.x * 256 + row;
#pragma unroll
    for (int i = 0; i < 4; i++) {
        float4* o4 = (float4*)(dst + (size_t)(pxb + 64 * i) * CQ + half);
#pragma unroll
        for (int jj = 0; jj < 4; jj++)
            o4[jj] = make_float4(v[i][4 * jj], v[i][4 * jj + 1],
                                 v[i][4 * jj + 2], v[i][4 * jj + 3]);
    }
}

// ---------------- K2: G = Kn @ x^T  (+ xsum, + KSum) --------------------------
// 512 blocks = 8 b x 64 n-slices of 256, 128 threads.
// Thread tile: 4 m (mg=tid>>4) x 6 c-pairs at c2 = cg + 16*j -> conflict-free.
__global__ void __launch_bounds__(128) k_gmat(const float* __restrict__ x)
{
    __shared__ __align__(16) float sXT[32][194];
    __shared__ __align__(16) float sKn[32][32];
    int tid = threadIdx.x;
    int w = tid >> 5, p = tid & 31;
    int mg = tid >> 4, cg = tid & 15;
    int b  = blockIdx.x >> 6;
    int n0 = (blockIdx.x & 63) << 8;

    const float* xb = x + (size_t)b * C_ * N_ + n0;
    const float4* knb = (const float4*)(g_Kn + ((size_t)b * N_ + n0) * CQ);

    u64 acc[4][6];
#pragma unroll
    for (int mi = 0; mi < 4; mi++)
#pragma unroll
        for (int j = 0; j < 6; j++) acc[mi][j] = 0ULL;
    float xs[48];
#pragma unroll
    for (int j = 0; j < 48; j++) xs[j] = 0.f;
    float ksacc = 0.f;

    for (int s = 0; s < 8; s++) {
        __syncthreads();
#pragma unroll
        for (int j = 0; j < 48; j++) {
            int c = w * 48 + j;
            float vx = xb[(size_t)c * N_ + s * 32 + p];
            sXT[p][c] = vx;
            xs[j] += vx;
        }
        {
            const float4* src = knb + s * 256;
            float4* d = (float4*)&sKn[0][0];
            d[tid] = src[tid];
            d[tid + 128] = src[tid + 128];
        }
        __syncthreads();

        if (tid < 32) {            // KSum partial: column tid of the Kn tile
#pragma unroll
            for (int pp = 0; pp < 32; pp++) ksacc += sKn[pp][tid];
        }

#pragma unroll 4
        for (int pp = 0; pp < 32; pp++) {
            float4 kv = *(const float4*)&sKn[pp][mg * 4];
            u64 k2a = pack2(kv.x, kv.x), k2b = pack2(kv.y, kv.y);
            u64 k2c = pack2(kv.z, kv.z), k2d = pack2(kv.w, kv.w);
#pragma unroll
            for (int j = 0; j < 6; j++) {
                u64 xv2 = *(const u64*)&sXT[pp][2 * (cg + 16 * j)];
                fma2(acc[0][j], k2a, xv2);
                fma2(acc[1][j], k2b, xv2);
                fma2(acc[2][j], k2c, xv2);
                fma2(acc[3][j], k2d, xv2);
            }
        }
    }

    float* gb = g_G + b * 33 * C_;
#pragma unroll
    for (int mi = 0; mi < 4; mi++)
#pragma unroll
        for (int j = 0; j < 6; j++) {
            float lo, hi; unpack2(acc[mi][j], lo, hi);
            red2(gb + (mg * 4 + mi) * C_ + 2 * (cg + 16 * j), lo, hi);
        }
#pragma unroll
    for (int j = 0; j < 48; j++) {
        float vv = xs[j];
        vv += __shfl_xor_sync(0xffffffffu, vv, 16);
        vv += __shfl_xor_sync(0xffffffffu, vv, 8);
        vv += __shfl_xor_sync(0xffffffffu, vv, 4);
        vv += __shfl_xor_sync(0xffffffffu, vv, 2);
        vv += __shfl_xor_sync(0xffffffffu, vv, 1);
        if (p == 0) atomicAdd(gb + 32 * C_ + w * 48 + j, vv);
    }
    if (tid < 32) atomicAdd(&g_KS[b * CQ + tid], ksacc);
}

// ---------------- K3: M' = Ghat @ Wv^T + outer(coef, bv) ---------------------
// 8 blocks (one per b), 192 threads (one per output column), 33 accumulators.
__global__ void __launch_bounds__(192) k_small(
    const float* __restrict__ Wv, const float* __restrict__ bv)
{
    extern __shared__ float sm[];
    float* sG  = sm;                 // [33][196]
    float* sWc = sm + 33 * 196;      // [192][33] chunk of Wv
    int tid = threadIdx.x;
    int b = blockIdx.x;

    for (int i = tid; i < 33 * C_; i += 192)
        sG[(i / C_) * 196 + (i % C_)] = g_G[b * 33 * C_ + i];

    float bvc = bv[tid];
    float acc[33];
#pragma unroll
    for (int m = 0; m < 32; m++) acc[m] = g_KS[b * CQ + m] * bvc;
    acc[32] = (float)N_ * bvc;

    for (int kc = 0; kc < C_; kc += 32) {
        __syncthreads();
        for (int i = tid; i < C_ * 32; i += 192) {
            int c = i >> 5, k = i & 31;
            sWc[c * 33 + k] = Wv[c * C_ + kc + k];
        }
        __syncthreads();
        float wreg[32];
#pragma unroll
        for (int k = 0; k < 32; k++) wreg[k] = sWc[tid * 33 + k];
#pragma unroll
        for (int m = 0; m < 33; m++) {
            float a = acc[m];
#pragma unroll
            for (int q = 0; q < 8; q++) {
                float4 g4 = *(const float4*)&sG[m * 196 + kc + 4 * q];
                a = fmaf(wreg[4 * q], g4.x, a);
                a = fmaf(wreg[4 * q + 1], g4.y, a);
                a = fmaf(wreg[4 * q + 2], g4.z, a);
                a = fmaf(wreg[4 * q + 3], g4.w, a);
            }
            acc[m] = a;
        }
    }
#pragma unroll
    for (int m = 0; m < 33; m++)
        g_M[(b * 33 + m) * C_ + tid] = acc[m];
}

// ---------------- K4: out[n,c] = A[n,0..32] @ M'[0..32,c] --------------------
// A[n][m] = g(n)*Qn[n][m], A[n][32] = g(n); A stored k-major (scalar LDS).
__global__ void __launch_bounds__(256) k_out(
    const float* __restrict__ gamma, float* __restrict__ out)
{
    extern __shared__ float sm[];
    float* sM  = sm;                  // [33][192]
    float* sAf = sm + 33 * C_;        // [33][132] k-major A
    __shared__ float sKS[CQ];
    int tid = threadIdx.x;
    int b  = blockIdx.x >> 7;
    int n0 = (blockIdx.x & 127) << 7;

    const float4* msrc = (const float4*)(g_M + b * 33 * C_);
    for (int i = tid; i < 33 * C_ / 4; i += 256) ((float4*)sM)[i] = msrc[i];
    if (tid < CQ) sKS[tid] = g_KS[b * CQ + tid] + EPSF;

    const float4* qsrc = (const float4*)(g_Qn + ((size_t)b * N_ + n0) * CQ);
    for (int i = tid; i < 1024; i += 256) {
        float4 qv = qsrc[i];
        int px = i >> 3, mb = (i & 7) * 4;
        sAf[(mb + 0) * 132 + px] = qv.x;
        sAf[(mb + 1) * 132 + px] = qv.y;
        sAf[(mb + 2) * 132 + px] = qv.z;
        sAf[(mb + 3) * 132 + px] = qv.w;
    }
    __syncthreads();

    float gam = gamma[0];
    if (tid < 128) {
        float dot = 0.f, qv[CQ];
#pragma unroll
        for (int m = 0; m < CQ; m++) { qv[m] = sAf[m * 132 + tid]; dot += qv[m] * sKS[m]; }
        float g = gam / ((float)N_ + dot);
#pragma unroll
        for (int m = 0; m < CQ; m++) sAf[m * 132 + tid] = qv[m] * g;
        sAf[32 * 132 + tid] = g;
    }
    __syncthreads();

    int rw = tid & 31, cg = tid >> 5;
    u64 acc[4][12];
#pragma unroll
    for (int i = 0; i < 4; i++)
#pragma unroll
        for (int j = 0; j < 12; j++) acc[i][j] = 0ULL;

#pragma unroll 3
    for (int k = 0; k < 33; k++) {
        u64 a2[4];
#pragma unroll
        for (int i = 0; i < 4; i++) {
            float av = sAf[k * 132 + rw + 32 * i];
            a2[i] = pack2(av, av);
        }
        const float4* m4 = (const float4*)(sM + k * C_) + cg * 6;
#pragma unroll
        for (int t = 0; t < 6; t++) {
            float4 mv = m4[t];
            u64 mlo = pack2(mv.x, mv.y), mhi = pack2(mv.z, mv.w);
#pragma unroll
            for (int i = 0; i < 4; i++) {
                fma2(acc[i][2 * t],     a2[i], mlo);
                fma2(acc[i][2 * t + 1], a2[i], mhi);
            }
        }
    }

    float* ob = out + (size_t)b * C_ * N_ + n0 + rw;
#pragma unroll
    for (int i = 0; i < 4; i++)
#pragma unroll
        for (int t = 0; t < 6; t++) {
            int c = cg * 24 + 4 * t;
            float lo, hi;
            unpack2(acc[i][2 * t], lo, hi);
            ob[(size_t)c * N_ + 32 * i]       = lo;
            ob[(size_t)(c + 1) * N_ + 32 * i] = hi;
            unpack2(acc[i][2 * t + 1], lo, hi);
            ob[(size_t)(c + 2) * N_ + 32 * i] = lo;
            ob[(size_t)(c + 3) * N_ + 32 * i] = hi;
        }
}

// ---------------- launch ------------------------------------------------------
extern "C" void kernel_launch(void* const* d_in, const int* in_sizes, int n_in,
                              void* d_out, int out_size)
{
    const float* x     = (const float*)d_in[0];
    const float* x1    = (const float*)d_in[1];
    const float* Wq    = (const float*)d_in[2];
    const float* bq    = (const float*)d_in[3];
    const float* Wk    = (const float*)d_in[4];
    const float* bk    = (const float*)d_in[5];
    const float* Wv    = (const float*)d_in[6];
    const float* bv    = (const float*)d_in[7];
    const float* gamma = (const float*)d_in[8];
    float* out = (float*)d_out;

    static int inited = 0;
    if (!inited) {
        cudaFuncSetAttribute(k_qk,    cudaFuncAttributeMaxDynamicSharedMemorySize, 71680);
        cudaFuncSetAttribute(k_small, cudaFuncAttributeMaxDynamicSharedMemorySize, 51216);
        cudaFuncSetAttribute(k_out,   cudaFuncAttributeMaxDynamicSharedMemorySize, 42768);
        inited = 1;
    }

    k_qk   <<<512, 256, 71680>>>(x1, Wq, bq, Wk, bk);
    k_gmat <<<512, 128>>>(x);
    k_small<<<8, 192, 51216>>>(Wv, bv);
    k_out  <<<1024, 256, 42768>>>(gamma, out);
}

// round 4
// speedup vs baseline: 1.5132x; 1.0076x over previous
#include <cuda_runtime.h>

#define B_   8
#define C_   192
#define CQ   32
#define N_   16384
#define NPIX (B_ * N_)
#define EPSF 1e-6f

typedef unsigned long long u64;

// ---------------- scratch ---------------------------------------------------
__device__ float g_Qn[(size_t)NPIX * CQ];   // [px][32] normalized Q
__device__ float g_Kn[(size_t)NPIX * CQ];   // [px][32] normalized K
__device__ float g_G[B_ * 33 * C_];         // rows 0..31: G[m][k]; row 32: xsum[k]
__device__ float g_KS[B_ * CQ];             // sum_n Kn
__device__ float g_M[B_ * 33 * C_];         // rows 0..31: matrix[m][c]; row 32: value_sum[c]

// ---------------- f32x2 helpers ---------------------------------------------
__device__ __forceinline__ u64 pack2(float lo, float hi) {
    u64 r;
    asm("mov.b64 %0, {%1, %2};" : "=l"(r)
        : "r"(__float_as_uint(lo)), "r"(__float_as_uint(hi)));
    return r;
}
__device__ __forceinline__ void unpack2(u64 v, float& lo, float& hi) {
    unsigned a, b;
    asm("mov.b64 {%0, %1}, %2;" : "=r"(a), "=r"(b) : "l"(v));
    lo = __uint_as_float(a); hi = __uint_as_float(b);
}
__device__ __forceinline__ void fma2(u64& d, u64 a, u64 b) {
    asm("fma.rn.f32x2 %0, %1, %2, %0;" : "+l"(d) : "l"(a), "l"(b));
}
__device__ __forceinline__ void red2(float* p, float lo, float hi) {
    asm volatile("red.global.add.v2.f32 [%0], {%1, %2};"
                 :: "l"(p), "f"(lo), "f"(hi) : "memory");
}

// ---------------- K1: Q/K projection + L2 norm (also zeroes G/KS) ------------
// 1024 blocks (8b x 128 slices of 128 px), 256 threads, 3 blocks/SM.
// Thread: 2 px (row, row+64) x 8 out-pairs (col group). Weights in smem as
// float4 (2 pairs) at col*80B spacing -> conflict-free 4-addr LDS.128.
__global__ void __launch_bounds__(256, 3) k_qk(
    const float* __restrict__ x1,
    const float* __restrict__ Wq, const float* __restrict__ bq,
    const float* __restrict__ Wk, const float* __restrict__ bk)
{
    extern __shared__ float sm[];
    // sW: per k: 4 col-groups * (4 float4 + 16B pad) = 320B; total 61440B
    float*  sW = sm;
    float*  sX = sm + 192 * 80;            // [16][128]  8192B   (total 69632B)

    int tid = threadIdx.x;
    int col = tid & 3, row = tid >> 2;
    int b   = blockIdx.x >> 7;
    int n0  = (blockIdx.x & 127) << 7;
    const float* xb = x1 + (size_t)b * C_ * N_ + n0;

    // zero accumulators for k_gmat
    {
        int z = blockIdx.x * 256 + tid;
        if (z < B_ * 33 * C_) g_G[z] = 0.0f;
        int zk = z - B_ * 33 * C_;
        if (zk >= 0 && zk < B_ * CQ) g_KS[zk] = 0.0f;
    }

    // stage weights: pair o (0..31) of [Q|K]; float2 at k*40+col*10+q*2+e (f2 units)
    for (int i = tid; i < 32 * C_; i += 256) {
        int o = i / C_, k = i % C_;        // coalesced in k
        int c0 = o >> 3, jj = o & 7, q = jj >> 1, e = jj & 1;
        float lo, hi;
        if (o < 16) { lo = Wq[(2 * o) * C_ + k];           hi = Wq[(2 * o + 1) * C_ + k]; }
        else { int oo = o - 16; lo = Wk[(2 * oo) * C_ + k]; hi = Wk[(2 * oo + 1) * C_ + k]; }
        ((float2*)sW)[k * 40 + c0 * 10 + q * 2 + e] = make_float2(lo, hi);
    }

    u64 acc[2][8];
#pragma unroll
    for (int jj = 0; jj < 8; jj++) {
        int o = col * 8 + jj;
        float lo, hi;
        if (o < 16) { lo = bq[2 * o]; hi = bq[2 * o + 1]; }
        else        { lo = bk[2 * (o - 16)]; hi = bk[2 * (o - 16) + 1]; }
        acc[0][jj] = pack2(lo, hi);
        acc[1][jj] = acc[0][jj];
    }

    const float4* sW4 = (const float4*)sW;
    for (int ks = 0; ks < C_; ks += 16) {
        __syncthreads();
#pragma unroll
        for (int i = 0; i < 8; i++) {
            int idx = i * 256 + tid;
            int t = idx >> 7, px = idx & 127;
            sX[t * 128 + px] = xb[(size_t)(ks + t) * N_ + px];
        }
        __syncthreads();
#pragma unroll
        for (int t = 0; t < 16; t++) {
            float xv0 = sX[t * 128 + row];
            float xv1 = sX[t * 128 + row + 64];
            u64 x20 = pack2(xv0, xv0);
            u64 x21 = pack2(xv1, xv1);
            int base = (ks + t) * 20 + col * 5;
#pragma unroll
            for (int q = 0; q < 4; q++) {
                float4 w4 = sW4[base + q];
                u64 wa = pack2(w4.x, w4.y);
                u64 wb = pack2(w4.z, w4.w);
                fma2(acc[0][2 * q],     wa, x20);
                fma2(acc[0][2 * q + 1], wb, x20);
                fma2(acc[1][2 * q],     wa, x21);
                fma2(acc[1][2 * q + 1], wb, x21);
            }
        }
    }

    // epilogue: unpack, L2 normalize (halves joined via shfl_xor 1)
    float v[2][16], s[2];
#pragma unroll
    for (int i = 0; i < 2; i++) {
        s[i] = 0.f;
#pragma unroll
        for (int jj = 0; jj < 8; jj++) {
            unpack2(acc[i][jj], v[i][2 * jj], v[i][2 * jj + 1]);
            s[i] += v[i][2 * jj] * v[i][2 * jj] + v[i][2 * jj + 1] * v[i][2 * jj + 1];
        }
    }
#pragma unroll
    for (int i = 0; i < 2; i++) {
        s[i] += __shfl_xor_sync(0xffffffffu, s[i], 1);
        float r = rsqrtf(s[i]);
#pragma unroll
        for (int t = 0; t < 16; t++) v[i][t] *= r;
    }

    float* dst = (col < 2) ? g_Qn : g_Kn;
    int half = (col & 1) << 4;
    int pxb = (int)(((size_t)b * N_ + n0)) + row;
#pragma unroll
    for (int i = 0; i < 2; i++) {
        float4* o4 = (float4*)(dst + (size_t)(pxb + 64 * i) * CQ + half);
#pragma unroll
        for (int jj = 0; jj < 4; jj++)
            o4[jj] = make_float4(v[i][4 * jj], v[i][4 * jj + 1],
                                 v[i][4 * jj + 2], v[i][4 * jj + 3]);
    }
}

// ---------------- K2: G = Kn @ x^T  (+ xsum, + KSum) --------------------------
// 512 blocks = 8 b x 64 n-slices of 256, 256 threads, 2 blocks/SM.
// Thread tile: 4 m (mg=tid&7) x 3 c-pairs (c2 = cg + 32*j, cg=tid>>3).
__global__ void __launch_bounds__(256, 2) k_gmat(const float* __restrict__ x)
{
    __shared__ __align__(16) float sXT[32][194];
    __shared__ __align__(16) float sKn[32][32];
    int tid = threadIdx.x;
    int w = tid >> 5, p = tid & 31;
    int mg = tid & 7, cg = tid >> 3;
    int b  = blockIdx.x >> 6;
    int n0 = (blockIdx.x & 63) << 8;

    const float* xb = x + (size_t)b * C_ * N_ + n0;
    const float4* knb = (const float4*)(g_Kn + ((size_t)b * N_ + n0) * CQ);

    u64 acc[4][3];
#pragma unroll
    for (int mi = 0; mi < 4; mi++)
#pragma unroll
        for (int j = 0; j < 3; j++) acc[mi][j] = 0ULL;
    float xs[24];
#pragma unroll
    for (int j = 0; j < 24; j++) xs[j] = 0.f;
    float ksacc = 0.f;

    for (int s = 0; s < 8; s++) {
        __syncthreads();
#pragma unroll
        for (int j = 0; j < 24; j++) {
            int c = w * 24 + j;
            float vx = xb[(size_t)c * N_ + s * 32 + p];
            sXT[p][c] = vx;
            xs[j] += vx;
        }
        ((float4*)&sKn[0][0])[tid] = knb[s * 256 + tid];
        __syncthreads();

        if (tid < 32) {            // KSum partial: column tid of the Kn tile
#pragma unroll
            for (int pp = 0; pp < 32; pp++) ksacc += sKn[pp][tid];
        }

#pragma unroll 4
        for (int pp = 0; pp < 32; pp++) {
            float4 kv = *(const float4*)&sKn[pp][mg * 4];
            u64 k2a = pack2(kv.x, kv.x), k2b = pack2(kv.y, kv.y);
            u64 k2c = pack2(kv.z, kv.z), k2d = pack2(kv.w, kv.w);
#pragma unroll
            for (int j = 0; j < 3; j++) {
                u64 xv2 = *(const u64*)&sXT[pp][2 * (cg + 32 * j)];
                fma2(acc[0][j], k2a, xv2);
                fma2(acc[1][j], k2b, xv2);
                fma2(acc[2][j], k2c, xv2);
                fma2(acc[3][j], k2d, xv2);
            }
        }
    }

    float* gb = g_G + b * 33 * C_;
#pragma unroll
    for (int mi = 0; mi < 4; mi++)
#pragma unroll
        for (int j = 0; j < 3; j++) {
            float lo, hi; unpack2(acc[mi][j], lo, hi);
            red2(gb + (mg * 4 + mi) * C_ + 2 * (cg + 32 * j), lo, hi);
        }
#pragma unroll
    for (int j = 0; j < 24; j++) {
        float vv = xs[j];
        vv += __shfl_xor_sync(0xffffffffu, vv, 16);
        vv += __shfl_xor_sync(0xffffffffu, vv, 8);
        vv += __shfl_xor_sync(0xffffffffu, vv, 4);
        vv += __shfl_xor_sync(0xffffffffu, vv, 2);
        vv += __shfl_xor_sync(0xffffffffu, vv, 1);
        if (p == 0) atomicAdd(gb + 32 * C_ + w * 24 + j, vv);
    }
    if (tid < 32) atomicAdd(&g_KS[b * CQ + tid], ksacc);
}

// ---------------- K3: M' = Ghat @ Wv^T + outer(coef, bv) ---------------------
// 48 blocks = 8 b x 6 col-tiles of 32; 128 threads: cl=tid&31, mg=tid>>5 (8-9 rows).
__global__ void __launch_bounds__(128) k_small(
    const float* __restrict__ Wv, const float* __restrict__ bv)
{
    extern __shared__ float sm[];
    float* sG  = sm;                  // [33][192]
    float* sWv = sm + 33 * C_;        // [32][193]
    int tid = threadIdx.x;
    int b  = blockIdx.x / 6;
    int ct = blockIdx.x % 6;
    int cl = tid & 31, mg = tid >> 5;
    int c  = ct * 32 + cl;

    for (int i = tid; i < 33 * C_; i += 128) sG[i] = g_G[b * 33 * C_ + i];
    for (int i = tid; i < 32 * C_; i += 128) {
        int cc = i / C_, k = i % C_;
        sWv[cc * 193 + k] = Wv[(size_t)(ct * 32 + cc) * C_ + k];
    }
    __syncthreads();

    float bvc = bv[c];
    float a[9];
#pragma unroll
    for (int rr = 0; rr < 8; rr++) a[rr] = g_KS[b * CQ + mg * 8 + rr] * bvc;
    a[8] = (float)N_ * bvc;

    const float* wp = sWv + cl * 193;
    for (int k = 0; k < C_; k += 2) {
        float w0 = wp[k], w1 = wp[k + 1];
#pragma unroll
        for (int rr = 0; rr < 8; rr++) {
            int r = mg * 8 + rr;
            a[rr] = fmaf(w0, sG[r * C_ + k], a[rr]);
            a[rr] = fmaf(w1, sG[r * C_ + k + 1], a[rr]);
        }
        if (mg == 3) {
            a[8] = fmaf(w0, sG[32 * C_ + k], a[8]);
            a[8] = fmaf(w1, sG[32 * C_ + k + 1], a[8]);
        }
    }
#pragma unroll
    for (int rr = 0; rr < 8; rr++)
        g_M[(b * 33 + mg * 8 + rr) * C_ + c] = a[rr];
    if (mg == 3)
        g_M[(b * 33 + 32) * C_ + c] = a[8];
}

// ---------------- K4: out[n,c] = A[n,0..32] @ M'[0..32,c] --------------------
// 2048 blocks (8b x 256 slices of 64 px), 256 threads, 3 blocks/SM.
// Thread: 2 px (rw, rw+32) x 12 c-pairs (float4 u = cg + 8*jj, broadcast LDS.128).
__global__ void __launch_bounds__(256, 3) k_out(
    const float* __restrict__ gamma, float* __restrict__ out)
{
    extern __shared__ float sm[];
    float* sM  = sm;                  // [33][192]  25344B
    float* sAf = sm + 33 * C_;        // [33][68]    8976B
    __shared__ float sKS[CQ];
    int tid = threadIdx.x;
    int b  = blockIdx.x >> 8;
    int n0 = (blockIdx.x & 255) << 6;

    const float4* msrc = (const float4*)(g_M + b * 33 * C_);
    for (int i = tid; i < 33 * C_ / 4; i += 256) ((float4*)sM)[i] = msrc[i];
    if (tid < CQ) sKS[tid] = g_KS[b * CQ + tid] + EPSF;

    const float4* qsrc = (const float4*)(g_Qn + ((size_t)b * N_ + n0) * CQ);
    for (int i = tid; i < 512; i += 256) {
        float4 qv = qsrc[i];
        int px = i >> 3, mb = (i & 7) * 4;
        sAf[(mb + 0) * 68 + px] = qv.x;
        sAf[(mb + 1) * 68 + px] = qv.y;
        sAf[(mb + 2) * 68 + px] = qv.z;
        sAf[(mb + 3) * 68 + px] = qv.w;
    }
    __syncthreads();

    float gam = gamma[0];
    if (tid < 64) {
        float dot = 0.f, qv[CQ];
#pragma unroll
        for (int m = 0; m < CQ; m++) { qv[m] = sAf[m * 68 + tid]; dot += qv[m] * sKS[m]; }
        float g = gam / ((float)N_ + dot);
#pragma unroll
        for (int m = 0; m < CQ; m++) sAf[m * 68 + tid] = qv[m] * g;
        sAf[32 * 68 + tid] = g;
    }
    __syncthreads();

    int rw = tid & 31, cg = tid >> 5;
    u64 acc[2][12];
#pragma unroll
    for (int i = 0; i < 2; i++)
#pragma unroll
        for (int j = 0; j < 12; j++) acc[i][j] = 0ULL;

#pragma unroll 3
    for (int k = 0; k < 33; k++) {
        float a0 = sAf[k * 68 + rw];
        float a1 = sAf[k * 68 + rw + 32];
        u64 a20 = pack2(a0, a0);
        u64 a21 = pack2(a1, a1);
        const float4* m4 = (const float4*)(sM + k * C_);
#pragma unroll
        for (int jj = 0; jj < 6; jj++) {
            float4 mv = m4[cg + 8 * jj];           // broadcast per warp
            u64 mlo = pack2(mv.x, mv.y), mhi = pack2(mv.z, mv.w);
            fma2(acc[0][2 * jj],     a20, mlo);
            fma2(acc[0][2 * jj + 1], a20, mhi);
            fma2(acc[1][2 * jj],     a21, mlo);
            fma2(acc[1][2 * jj + 1], a21, mhi);
        }
    }

    float* ob = out + (size_t)b * C_ * N_ + n0 + rw;
#pragma unroll
    for (int i = 0; i < 2; i++)
#pragma unroll
        for (int jj = 0; jj < 6; jj++) {
            int c = 4 * (cg + 8 * jj);
            float lo, hi;
            unpack2(acc[i][2 * jj], lo, hi);
            ob[(size_t)c * N_ + 32 * i]       = lo;
            ob[(size_t)(c + 1) * N_ + 32 * i] = hi;
            unpack2(acc[i][2 * jj + 1], lo, hi);
            ob[(size_t)(c + 2) * N_ + 32 * i] = lo;
            ob[(size_t)(c + 3) * N_ + 32 * i] = hi;
        }
}

// ---------------- launch ------------------------------------------------------
extern "C" void kernel_launch(void* const* d_in, const int* in_sizes, int n_in,
                              void* d_out, int out_size)
{
    const float* x     = (const float*)d_in[0];
    const float* x1    = (const float*)d_in[1];
    const float* Wq    = (const float*)d_in[2];
    const float* bq    = (const float*)d_in[3];
    const float* Wk    = (const float*)d_in[4];
    const float* bk    = (const float*)d_in[5];
    const float* Wv    = (const float*)d_in[6];
    const float* bv    = (const float*)d_in[7];
    const float* gamma = (const float*)d_in[8];
    float* out = (float*)d_out;

    static int inited = 0;
    if (!inited) {
        cudaFuncSetAttribute(k_qk,    cudaFuncAttributeMaxDynamicSharedMemorySize, 69632);
        cudaFuncSetAttribute(k_small, cudaFuncAttributeMaxDynamicSharedMemorySize, 50080);
        cudaFuncSetAttribute(k_out,   cudaFuncAttributeMaxDynamicSharedMemorySize, 34320);
        inited = 1;
    }

    k_qk   <<<1024, 256, 69632>>>(x1, Wq, bq, Wk, bk);
    k_gmat <<<512, 256>>>(x);
    k_small<<<48, 128, 50080>>>(Wv, bv);
    k_out  <<<2048, 256, 34320>>>(gamma, out);
}